// round 1
// baseline (speedup 1.0000x reference)
#include <cuda_runtime.h>
#include <math.h>

#define SEQ 4096
#define DMODEL 512
#define NHEAD 8
#define HDIM 64
#define FDIM 2048
#define NEXP 8
#define NPAIR (SEQ * 2)

// ---------------- scratch (device globals; no allocations allowed) ----------
__device__ float g_xn[SEQ * DMODEL];           // layernorm output (reused ln1/ln2)
__device__ float g_qkv[SEQ * 3 * DMODEL];      // qkv projection
__device__ float g_attn[SEQ * DMODEL];         // attention output (pre out-proj)
__device__ float g_xg[NPAIR * DMODEL];         // gathered tokens for MoE
__device__ float g_h1[NPAIR * FDIM];           // expert up-proj 1 (then fused g)
__device__ float g_h2[NPAIR * FDIM];           // expert up-proj 2
__device__ int   g_tidx[NPAIR];                // top2 expert index per (token,k)
__device__ float g_tscale[NPAIR];              // top2 gate prob per (token,k)
__device__ int   g_counts[NEXP];
__device__ int   g_cursor[NEXP];
__device__ int   g_off[NEXP];
__device__ int   g_rowTok[NPAIR];
__device__ float g_rowScale[NPAIR];

// ---------------- layernorm: one block per row, 128 threads ------------------
__global__ __launch_bounds__(128) void layernorm_k(
    const float* __restrict__ x, const float* __restrict__ g,
    const float* __restrict__ b, float* __restrict__ y)
{
    int t = blockIdx.x;
    int tid = threadIdx.x;
    float4 v = ((const float4*)(x + (size_t)t * DMODEL))[tid];
    float s  = v.x + v.y + v.z + v.w;
    float ss = v.x * v.x + v.y * v.y + v.z * v.z + v.w * v.w;
    #pragma unroll
    for (int o = 16; o > 0; o >>= 1) {
        s  += __shfl_xor_sync(0xffffffffu, s, o);
        ss += __shfl_xor_sync(0xffffffffu, ss, o);
    }
    __shared__ float sw[4], ssw[4];
    __shared__ float meanS, rstdS;
    int lane = tid & 31, w = tid >> 5;
    if (lane == 0) { sw[w] = s; ssw[w] = ss; }
    __syncthreads();
    if (tid == 0) {
        float S = sw[0] + sw[1] + sw[2] + sw[3];
        float SS = ssw[0] + ssw[1] + ssw[2] + ssw[3];
        float mean = S / (float)DMODEL;
        float var = SS / (float)DMODEL - mean * mean;
        meanS = mean;
        rstdS = rsqrtf(var + 1e-5f);
    }
    __syncthreads();
    float mean = meanS, rstd = rstdS;
    float4 gg = ((const float4*)g)[tid];
    float4 bb = ((const float4*)b)[tid];
    float4 o;
    o.x = (v.x - mean) * rstd * gg.x + bb.x;
    o.y = (v.y - mean) * rstd * gg.y + bb.y;
    o.z = (v.z - mean) * rstd * gg.z + bb.z;
    o.w = (v.w - mean) * rstd * gg.w + bb.w;
    ((float4*)(y + (size_t)t * DMODEL))[tid] = o;
}

// ---------------- shared GEMM core: C[M,N] = A[M,K] * B[N,K]^T ---------------
// BM=BN=128, BK=16, 256 threads, 8x8 per-thread register tile.
__device__ __forceinline__ void gemm_core(
    const float* __restrict__ A, const float* __restrict__ B,
    int M, int K, int bm, int bn,
    float (*As)[132], float (*Bs)[132], float acc[8][8])
{
    const int tid = threadIdx.x;
    const int ry = (tid >> 4) << 3;
    const int rx = (tid & 15) << 3;
    for (int k0 = 0; k0 < K; k0 += 16) {
        #pragma unroll
        for (int i = 0; i < 2; i++) {
            int f = tid + i * 256;
            int r = f >> 2;
            int c4 = (f & 3) << 2;
            float4 v = make_float4(0.f, 0.f, 0.f, 0.f);
            int gr = bm + r;
            if (gr < M) v = *(const float4*)(A + (size_t)gr * K + k0 + c4);
            As[c4 + 0][r] = v.x; As[c4 + 1][r] = v.y;
            As[c4 + 2][r] = v.z; As[c4 + 3][r] = v.w;
            float4 wv = *(const float4*)(B + (size_t)(bn + r) * K + k0 + c4);
            Bs[c4 + 0][r] = wv.x; Bs[c4 + 1][r] = wv.y;
            Bs[c4 + 2][r] = wv.z; Bs[c4 + 3][r] = wv.w;
        }
        __syncthreads();
        #pragma unroll
        for (int kk = 0; kk < 16; kk++) {
            float4 a0 = *(const float4*)&As[kk][ry];
            float4 a1 = *(const float4*)&As[kk][ry + 4];
            float4 b0 = *(const float4*)&Bs[kk][rx];
            float4 b1 = *(const float4*)&Bs[kk][rx + 4];
            float a[8] = {a0.x, a0.y, a0.z, a0.w, a1.x, a1.y, a1.z, a1.w};
            float b[8] = {b0.x, b0.y, b0.z, b0.w, b1.x, b1.y, b1.z, b1.w};
            #pragma unroll
            for (int i = 0; i < 8; i++)
                #pragma unroll
                for (int j = 0; j < 8; j++)
                    acc[i][j] = fmaf(a[i], b[j], acc[i][j]);
        }
        __syncthreads();
    }
}

// Plain GEMM with bias + optional residual add.
__global__ __launch_bounds__(256) void gemm_nt(
    const float* __restrict__ A, const float* __restrict__ B,
    const float* __restrict__ bias, const float* __restrict__ resid,
    float* __restrict__ C, int M, int N, int K)
{
    __shared__ float As[16][132];
    __shared__ float Bs[16][132];
    const int bm = blockIdx.y * 128;
    const int bn = blockIdx.x * 128;
    float acc[8][8];
    #pragma unroll
    for (int i = 0; i < 8; i++)
        #pragma unroll
        for (int j = 0; j < 8; j++) acc[i][j] = 0.f;
    gemm_core(A, B, M, K, bm, bn, As, Bs, acc);
    const int tid = threadIdx.x;
    const int ry = (tid >> 4) << 3;
    const int rx = (tid & 15) << 3;
    #pragma unroll
    for (int i = 0; i < 8; i++) {
        int r = bm + ry + i;
        if (r >= M) break;
        #pragma unroll
        for (int j = 0; j < 8; j++) {
            int c = bn + rx + j;
            float v = acc[i][j] + bias[c];
            if (resid) v += resid[(size_t)r * N + c];
            C[(size_t)r * N + c] = v;
        }
    }
}

// MoE up-projection GEMM: per-expert gathered rows, W [E][F][D], bias [E][F].
__global__ __launch_bounds__(256) void moe_up_gemm(
    const float* __restrict__ W, const float* __restrict__ Ball,
    float* __restrict__ Out)
{
    int e = blockIdx.z;
    int M = g_counts[e];
    int bm = blockIdx.y * 128;
    if (bm >= M) return;
    int bn = blockIdx.x * 128;
    const float* A = g_xg + (size_t)g_off[e] * DMODEL;
    const float* B = W + (size_t)e * FDIM * DMODEL;
    const float* bias = Ball + (size_t)e * FDIM;
    float* C = Out + (size_t)g_off[e] * FDIM;
    __shared__ float As[16][132];
    __shared__ float Bs[16][132];
    float acc[8][8];
    #pragma unroll
    for (int i = 0; i < 8; i++)
        #pragma unroll
        for (int j = 0; j < 8; j++) acc[i][j] = 0.f;
    gemm_core(A, B, M, DMODEL, bm, bn, As, Bs, acc);
    const int tid = threadIdx.x;
    const int ry = (tid >> 4) << 3;
    const int rx = (tid & 15) << 3;
    #pragma unroll
    for (int i = 0; i < 8; i++) {
        int r = bm + ry + i;
        if (r >= M) break;
        #pragma unroll
        for (int j = 0; j < 8; j++) {
            int c = bn + rx + j;
            C[(size_t)r * FDIM + c] = acc[i][j] + bias[c];
        }
    }
}

// MoE down GEMM + scaled scatter-add into the residual output.
// A = g_h1 (post silu*mul), B = wo [E][D][F], bias = bo [E][D].
__global__ __launch_bounds__(256) void moe_down_gemm(
    const float* __restrict__ Wo, const float* __restrict__ Bo,
    float* __restrict__ Out)
{
    int e = blockIdx.z;
    int M = g_counts[e];
    int bm = blockIdx.y * 128;
    if (bm >= M) return;
    int bn = blockIdx.x * 128;
    const float* A = g_h1 + (size_t)g_off[e] * FDIM;
    const float* B = Wo + (size_t)e * DMODEL * FDIM;
    const float* bias = Bo + (size_t)e * DMODEL;
    __shared__ float As[16][132];
    __shared__ float Bs[16][132];
    float acc[8][8];
    #pragma unroll
    for (int i = 0; i < 8; i++)
        #pragma unroll
        for (int j = 0; j < 8; j++) acc[i][j] = 0.f;
    gemm_core(A, B, M, FDIM, bm, bn, As, Bs, acc);
    const int tid = threadIdx.x;
    const int ry = (tid >> 4) << 3;
    const int rx = (tid & 15) << 3;
    #pragma unroll
    for (int i = 0; i < 8; i++) {
        int r = bm + ry + i;
        if (r >= M) break;
        int gr = g_off[e] + r;
        int tok = g_rowTok[gr];
        float sc = g_rowScale[gr];
        #pragma unroll
        for (int j = 0; j < 8; j++) {
            int c = bn + rx + j;
            atomicAdd(&Out[(size_t)tok * DMODEL + c], sc * (acc[i][j] + bias[c]));
        }
    }
}

// ---------------- flash attention: Bq=64, Bk=32, hd=64, 256 threads ----------
__global__ __launch_bounds__(256) void flash_attn(
    const float* __restrict__ qkv, float* __restrict__ out)
{
    const int h = blockIdx.y;
    const int q0 = blockIdx.x * 64;
    const int tid = threadIdx.x;
    const int tx = tid & 15, ty = tid >> 4;
    const int ty4 = ty * 4, tx2 = tx * 2, tx4 = tx * 4;

    __shared__ float Qs[64][64];   // [d][row]
    __shared__ float Ks[64][32];   // [d][col]
    __shared__ float Vs[32][64];   // [k][d]
    __shared__ float Ss[64][33];   // scores / probs, padded
    __shared__ float mS[64], lS[64], aS[64];

    // load Q tile transposed
    #pragma unroll
    for (int i = 0; i < 4; i++) {
        int f = tid + i * 256;       // 1024 float4 total
        int r = f >> 4;
        int d4 = (f & 15) << 2;
        float4 v = *(const float4*)(qkv + (size_t)(q0 + r) * 1536 + h * 64 + d4);
        Qs[d4 + 0][r] = v.x; Qs[d4 + 1][r] = v.y;
        Qs[d4 + 2][r] = v.z; Qs[d4 + 3][r] = v.w;
    }
    if (tid < 64) { mS[tid] = -1e30f; lS[tid] = 0.f; }

    float acc[4][4];
    #pragma unroll
    for (int i = 0; i < 4; i++)
        #pragma unroll
        for (int j = 0; j < 4; j++) acc[i][j] = 0.f;

    for (int k0 = 0; k0 < SEQ; k0 += 32) {
        #pragma unroll
        for (int i = 0; i < 2; i++) {
            int f = tid + i * 256;   // 512 float4
            int col = f >> 4;
            int d4 = (f & 15) << 2;
            const float* baseK = qkv + (size_t)(k0 + col) * 1536 + 512 + h * 64 + d4;
            float4 kv = *(const float4*)baseK;
            Ks[d4 + 0][col] = kv.x; Ks[d4 + 1][col] = kv.y;
            Ks[d4 + 2][col] = kv.z; Ks[d4 + 3][col] = kv.w;
            float4 vv = *(const float4*)(baseK + 512);
            *(float4*)&Vs[col][d4] = vv;
        }
        __syncthreads();

        // S = Q K^T * scale
        float s[4][2];
        #pragma unroll
        for (int i = 0; i < 4; i++) { s[i][0] = 0.f; s[i][1] = 0.f; }
        #pragma unroll
        for (int d = 0; d < 64; d++) {
            float4 a = *(const float4*)&Qs[d][ty4];
            float b0 = Ks[d][tx2], b1 = Ks[d][tx2 + 1];
            s[0][0] = fmaf(a.x, b0, s[0][0]); s[0][1] = fmaf(a.x, b1, s[0][1]);
            s[1][0] = fmaf(a.y, b0, s[1][0]); s[1][1] = fmaf(a.y, b1, s[1][1]);
            s[2][0] = fmaf(a.z, b0, s[2][0]); s[2][1] = fmaf(a.z, b1, s[2][1]);
            s[3][0] = fmaf(a.w, b0, s[3][0]); s[3][1] = fmaf(a.w, b1, s[3][1]);
        }
        #pragma unroll
        for (int i = 0; i < 4; i++) {
            Ss[ty4 + i][tx2]     = s[i][0] * 0.125f;
            Ss[ty4 + i][tx2 + 1] = s[i][1] * 0.125f;
        }
        __syncthreads();

        // online softmax per row
        if (tid < 64) {
            int r = tid;
            float mprev = mS[r];
            float mx = mprev;
            #pragma unroll
            for (int j = 0; j < 32; j++) mx = fmaxf(mx, Ss[r][j]);
            float alpha = __expf(mprev - mx);
            float sum = 0.f;
            #pragma unroll
            for (int j = 0; j < 32; j++) {
                float p = __expf(Ss[r][j] - mx);
                Ss[r][j] = p;
                sum += p;
            }
            lS[r] = lS[r] * alpha + sum;
            mS[r] = mx;
            aS[r] = alpha;
        }
        __syncthreads();

        #pragma unroll
        for (int i = 0; i < 4; i++) {
            float al = aS[ty4 + i];
            #pragma unroll
            for (int j = 0; j < 4; j++) acc[i][j] *= al;
        }
        #pragma unroll
        for (int kk = 0; kk < 32; kk++) {
            float4 vv = *(const float4*)&Vs[kk][tx4];
            float p0 = Ss[ty4 + 0][kk];
            float p1 = Ss[ty4 + 1][kk];
            float p2 = Ss[ty4 + 2][kk];
            float p3 = Ss[ty4 + 3][kk];
            acc[0][0] = fmaf(p0, vv.x, acc[0][0]); acc[0][1] = fmaf(p0, vv.y, acc[0][1]);
            acc[0][2] = fmaf(p0, vv.z, acc[0][2]); acc[0][3] = fmaf(p0, vv.w, acc[0][3]);
            acc[1][0] = fmaf(p1, vv.x, acc[1][0]); acc[1][1] = fmaf(p1, vv.y, acc[1][1]);
            acc[1][2] = fmaf(p1, vv.z, acc[1][2]); acc[1][3] = fmaf(p1, vv.w, acc[1][3]);
            acc[2][0] = fmaf(p2, vv.x, acc[2][0]); acc[2][1] = fmaf(p2, vv.y, acc[2][1]);
            acc[2][2] = fmaf(p2, vv.z, acc[2][2]); acc[2][3] = fmaf(p2, vv.w, acc[2][3]);
            acc[3][0] = fmaf(p3, vv.x, acc[3][0]); acc[3][1] = fmaf(p3, vv.y, acc[3][1]);
            acc[3][2] = fmaf(p3, vv.z, acc[3][2]); acc[3][3] = fmaf(p3, vv.w, acc[3][3]);
        }
        __syncthreads();
    }

    #pragma unroll
    for (int i = 0; i < 4; i++) {
        int r = ty4 + i;
        float inv = 1.f / lS[r];
        #pragma unroll
        for (int j = 0; j < 4; j++) {
            out[(size_t)(q0 + r) * DMODEL + h * 64 + tx4 + j] = acc[i][j] * inv;
        }
    }
}

// ---------------- gating: one warp per token ---------------------------------
__global__ __launch_bounds__(128) void gate_topk(
    const float* __restrict__ xn, const float* __restrict__ gw,
    const float* __restrict__ gb)
{
    int warp = threadIdx.x >> 5;
    int lane = threadIdx.x & 31;
    int t = blockIdx.x * 4 + warp;
    float acc[NEXP];
    #pragma unroll
    for (int e = 0; e < NEXP; e++) acc[e] = 0.f;
    for (int d = lane; d < DMODEL; d += 32) {
        float xv = xn[(size_t)t * DMODEL + d];
        #pragma unroll
        for (int e = 0; e < NEXP; e++) acc[e] = fmaf(xv, gw[e * DMODEL + d], acc[e]);
    }
    #pragma unroll
    for (int e = 0; e < NEXP; e++)
        #pragma unroll
        for (int o = 16; o > 0; o >>= 1)
            acc[e] += __shfl_xor_sync(0xffffffffu, acc[e], o);
    if (lane == 0) {
        float lg[NEXP];
        float mx = -1e30f;
        #pragma unroll
        for (int e = 0; e < NEXP; e++) { lg[e] = acc[e] + gb[e]; mx = fmaxf(mx, lg[e]); }
        float sum = 0.f;
        #pragma unroll
        for (int e = 0; e < NEXP; e++) { lg[e] = __expf(lg[e] - mx); sum += lg[e]; }
        float inv = 1.f / sum;
        int e0 = 0; float p0 = lg[0];
        #pragma unroll
        for (int e = 1; e < NEXP; e++) if (lg[e] > p0) { p0 = lg[e]; e0 = e; }
        int e1 = -1; float p1 = -1.f;
        #pragma unroll
        for (int e = 0; e < NEXP; e++)
            if (e != e0 && lg[e] > p1) { p1 = lg[e]; e1 = e; }
        g_tidx[t * 2] = e0;         g_tidx[t * 2 + 1] = e1;
        g_tscale[t * 2] = p0 * inv; g_tscale[t * 2 + 1] = p1 * inv;
        atomicAdd(&g_counts[e0], 1);
        atomicAdd(&g_counts[e1], 1);
    }
}

__global__ void zero_counts_k() {
    if (threadIdx.x < NEXP) { g_counts[threadIdx.x] = 0; g_cursor[threadIdx.x] = 0; }
}

__global__ void calc_offsets_k() {
    int o = 0;
    for (int e = 0; e < NEXP; e++) { g_off[e] = o; o += g_counts[e]; }
}

// gather tokens into expert-contiguous rows; one block per (token, k) pair
__global__ __launch_bounds__(128) void gather_pairs(const float* __restrict__ xn)
{
    int p = blockIdx.x;
    __shared__ int posS;
    if (threadIdx.x == 0) {
        int e = g_tidx[p];
        int pos = g_off[e] + atomicAdd(&g_cursor[e], 1);
        g_rowTok[pos] = p >> 1;
        g_rowScale[pos] = g_tscale[p];
        posS = pos;
    }
    __syncthreads();
    int pos = posS;
    int t = p >> 1;
    ((float4*)(g_xg + (size_t)pos * DMODEL))[threadIdx.x] =
        ((const float4*)(xn + (size_t)t * DMODEL))[threadIdx.x];
}

// h1 = silu(h1) * h2, elementwise over all NPAIR*FDIM values (all rows valid)
__global__ __launch_bounds__(256) void silu_mul_k()
{
    size_t i = (size_t)blockIdx.x * blockDim.x + threadIdx.x;  // float4 index
    float4 a = ((const float4*)g_h1)[i];
    float4 b = ((const float4*)g_h2)[i];
    a.x = a.x / (1.f + __expf(-a.x)) * b.x;
    a.y = a.y / (1.f + __expf(-a.y)) * b.y;
    a.z = a.z / (1.f + __expf(-a.z)) * b.z;
    a.w = a.w / (1.f + __expf(-a.w)) * b.w;
    ((float4*)g_h1)[i] = a;
}

// ---------------- launch -----------------------------------------------------
extern "C" void kernel_launch(void* const* d_in, const int* in_sizes, int n_in,
                              void* d_out, int out_size)
{
    const float* src        = (const float*)d_in[0];
    const float* in_proj_w  = (const float*)d_in[1];
    const float* in_proj_b  = (const float*)d_in[2];
    const float* out_proj_w = (const float*)d_in[3];
    const float* out_proj_b = (const float*)d_in[4];
    const float* ln1_g      = (const float*)d_in[5];
    const float* ln1_b      = (const float*)d_in[6];
    const float* ln2_g      = (const float*)d_in[7];
    const float* ln2_b      = (const float*)d_in[8];
    const float* gate_w     = (const float*)d_in[9];
    const float* gate_b     = (const float*)d_in[10];
    const float* w1         = (const float*)d_in[11];
    const float* b1         = (const float*)d_in[12];
    const float* w2         = (const float*)d_in[13];
    const float* b2         = (const float*)d_in[14];
    const float* wo         = (const float*)d_in[15];
    const float* bo         = (const float*)d_in[16];
    float* out = (float*)d_out;

    float *xn, *qkv, *attn, *h1, *h2;
    cudaGetSymbolAddress((void**)&xn,   g_xn);
    cudaGetSymbolAddress((void**)&qkv,  g_qkv);
    cudaGetSymbolAddress((void**)&attn, g_attn);
    cudaGetSymbolAddress((void**)&h1,   g_h1);
    cudaGetSymbolAddress((void**)&h2,   g_h2);

    zero_counts_k<<<1, 32>>>();

    // ---- attention block ----
    layernorm_k<<<SEQ, 128>>>(src, ln1_g, ln1_b, xn);
    gemm_nt<<<dim3(12, 32), 256>>>(xn, in_proj_w, in_proj_b, nullptr, qkv,
                                   SEQ, 3 * DMODEL, DMODEL);
    flash_attn<<<dim3(64, NHEAD), 256>>>(qkv, attn);
    gemm_nt<<<dim3(4, 32), 256>>>(attn, out_proj_w, out_proj_b, src, out,
                                  SEQ, DMODEL, DMODEL);   // out = x1 (residual)

    // ---- MoE block ----
    layernorm_k<<<SEQ, 128>>>(out, ln2_g, ln2_b, xn);
    gate_topk<<<SEQ / 4, 128>>>(xn, gate_w, gate_b);
    calc_offsets_k<<<1, 1>>>();
    gather_pairs<<<NPAIR, 128>>>(xn);
    moe_up_gemm<<<dim3(FDIM / 128, SEQ / 128, NEXP), 256>>>(w1, b1, h1);
    moe_up_gemm<<<dim3(FDIM / 128, SEQ / 128, NEXP), 256>>>(w2, b2, h2);
    silu_mul_k<<<(NPAIR * FDIM / 4) / 256, 256>>>();
    moe_down_gemm<<<dim3(DMODEL / 128, SEQ / 128, NEXP), 256>>>(wo, bo, out);
}